// round 15
// baseline (speedup 1.0000x reference)
#include <cuda_runtime.h>
#include <cuda_bf16.h>
#include <math.h>
#include <stdint.h>

// ---------------- problem constants ----------------
#define NN 4096
#define DD 4096
#define OO 4096
#define EE 8
#define RR 16
#define ER 128      // E*R
#define GG 9        // E+1
#define NSPLIT 8    // K-splits for the loraA tensor-core GEMM

// ---------------- device scratch ----------------
__device__ float g_gates[NN * GG];              // softmax gates per row
__device__ float g_t[NN * ER];                  // gated LoRA intermediate t'
__device__ float g_At[DD * ER];                 // lora_A transposed to [d][e*16+r]
__device__ float g_tp[NSPLIT * NN * ER];        // K-split partials of x@At (16 MB)

// ---------------- tf32 / async helpers (sm_80+ baseline ISA) ----------------
__device__ __forceinline__ uint32_t to_tf32(float v) {
    uint32_t r;
    asm("cvt.rna.tf32.f32 %0, %1;" : "=r"(r) : "f"(v));
    return r;
}
__device__ __forceinline__ void mma_tf32(float* c, const uint32_t* a, const uint32_t* b) {
    asm volatile(
        "mma.sync.aligned.m16n8k8.row.col.f32.tf32.tf32.f32 "
        "{%0,%1,%2,%3}, {%4,%5,%6,%7}, {%8,%9}, {%0,%1,%2,%3};"
        : "+f"(c[0]), "+f"(c[1]), "+f"(c[2]), "+f"(c[3])
        : "r"(a[0]), "r"(a[1]), "r"(a[2]), "r"(a[3]), "r"(b[0]), "r"(b[1]));
}
__device__ __forceinline__ uint32_t smem_u32(const void* p) {
    uint32_t a;
    asm("{ .reg .u64 t; cvta.to.shared.u64 t, %1; cvt.u32.u64 %0, t; }" : "=r"(a) : "l"(p));
    return a;
}
__device__ __forceinline__ void cp16(uint32_t smem, const void* gmem) {
    asm volatile("cp.async.cg.shared.global [%0], [%1], 16;" :: "r"(smem), "l"(gmem) : "memory");
}
__device__ __forceinline__ void cp_commit() {
    asm volatile("cp.async.commit_group;" ::: "memory");
}
__device__ __forceinline__ void cp_wait1() {
    asm volatile("cp.async.wait_group 1;" ::: "memory");
}

// ---------------- kernel 1: gate logits + top2 + softmax (R1-proven) ----------------
__global__ void gate_kernel(const float* __restrict__ x,
                            const float* __restrict__ gw)
{
    int warp = (blockIdx.x * blockDim.x + threadIdx.x) >> 5;
    int lane = threadIdx.x & 31;
    if (warp >= NN) return;
    const float* xr = x + (size_t)warp * DD;

    float acc[GG];
#pragma unroll
    for (int c = 0; c < GG; c++) acc[c] = 0.f;

    for (int d = lane; d < DD; d += 32) {
        float xv = xr[d];
#pragma unroll
        for (int c = 0; c < GG; c++)
            acc[c] += xv * gw[c * DD + d];
    }
#pragma unroll
    for (int c = 0; c < GG; c++) {
#pragma unroll
        for (int off = 16; off > 0; off >>= 1)
            acc[c] += __shfl_xor_sync(0xFFFFFFFFu, acc[c], off);
    }

    if (lane == 0) {
        float m1 = -INFINITY, m2 = -INFINITY;
        int i1 = -1, i2 = -1;
#pragma unroll
        for (int c = 1; c < GG; c++) {
            float v = acc[c];
            if (v > m1) { m2 = m1; i2 = i1; m1 = v; i1 = c; }
            else if (v > m2) { m2 = v; i2 = c; }
        }
        float vals[GG];
        vals[0] = acc[0];
#pragma unroll
        for (int c = 1; c < GG; c++)
            vals[c] = (c == i1 || c == i2) ? acc[c] : 0.0f;

        float mx = vals[0];
#pragma unroll
        for (int c = 1; c < GG; c++) mx = fmaxf(mx, vals[c]);
        float s = 0.f;
        float e[GG];
#pragma unroll
        for (int c = 0; c < GG; c++) { e[c] = __expf(vals[c] - mx); s += e[c]; }
        float inv = 1.0f / s;
#pragma unroll
        for (int c = 0; c < GG; c++)
            g_gates[warp * GG + c] = e[c] * inv;
    }
}

// ---------------- kernel 2: transpose lora_A -> [d][e*16+r] (R1-proven) ----------------
__global__ void transpose_A_kernel(const float* __restrict__ loraA)
{
    int total = EE * DD * RR;
    for (int i = blockIdx.x * blockDim.x + threadIdx.x; i < total;
         i += gridDim.x * blockDim.x) {
        int e = i / (DD * RR);
        int d = (i / RR) % DD;
        int r = i % RR;
        g_At[d * ER + e * RR + r] = loraA[i];
    }
}

// ---------------- shared geometry (R11-proven) ----------------
#define SA16 20  // loraA kernel: A stride (16 + pad4)
#define SB 136   // B smem stride in u32 (128 + pad8): frag banks 8*tig+gid distinct

// ---------------- kernel 3: loraA tensor-core GEMM, K-split (R13-proven, verbatim) ----------------
__global__ void __launch_bounds__(128, 2) loraA_tc_kernel(const float* __restrict__ x)
{
    __shared__ __align__(16) uint32_t At2[2][128][SA16];
    __shared__ __align__(16) uint32_t Bt2[2][16][SB];

    int tid  = threadIdx.x;
    int wid  = tid >> 5;
    int lane = tid & 31;
    int gid  = lane >> 2;
    int tig  = lane & 3;
    int wm = wid >> 1;
    int wn = wid & 1;
    int split   = blockIdx.x;               // 0..7
    int rowBase = blockIdx.y * 128;
    int kBase   = split * (DD / NSPLIT);    // 512 per split

    float acc[4][8][4];
#pragma unroll
    for (int mi = 0; mi < 4; mi++)
#pragma unroll
        for (int ni = 0; ni < 8; ni++)
#pragma unroll
            for (int q = 0; q < 4; q++) acc[mi][ni][q] = 0.f;

    int arow = tid >> 2, aq = tid & 3;
    int bkr  = tid >> 5, bq = tid & 31;

    float4 ra[4], rb[4];

    auto ldreg = [&](int c) {
        int k0 = kBase + c * 16;
#pragma unroll
        for (int j = 0; j < 4; j++) {
            ra[j] = *(const float4*)&x[(size_t)(rowBase + arow + 32 * j) * DD + k0 + aq * 4];
            rb[j] = *(const float4*)&g_At[(size_t)(k0 + bkr + 4 * j) * ER + bq * 4];
        }
    };
    auto convst = [&](int s) {
#pragma unroll
        for (int j = 0; j < 4; j++) {
            *(uint4*)&At2[s][arow + 32 * j][aq * 4] =
                make_uint4(to_tf32(ra[j].x), to_tf32(ra[j].y), to_tf32(ra[j].z), to_tf32(ra[j].w));
            *(uint4*)&Bt2[s][bkr + 4 * j][bq * 4] =
                make_uint4(to_tf32(rb[j].x), to_tf32(rb[j].y), to_tf32(rb[j].z), to_tf32(rb[j].w));
        }
    };
    auto compute = [&](int buf) {
#pragma unroll
        for (int s = 0; s < 2; s++) {
            int k0 = s * 8 + tig;
            uint32_t bf[8][2];
#pragma unroll
            for (int ni = 0; ni < 8; ni++) {
                int n = wn * 64 + ni * 8 + gid;
                bf[ni][0] = Bt2[buf][k0][n];
                bf[ni][1] = Bt2[buf][k0 + 4][n];
            }
#pragma unroll
            for (int mi = 0; mi < 4; mi++) {
                int r = wm * 64 + mi * 16 + gid;
                uint32_t af[4];
                af[0] = At2[buf][r][k0];
                af[1] = At2[buf][r + 8][k0];
                af[2] = At2[buf][r][k0 + 4];
                af[3] = At2[buf][r + 8][k0 + 4];
#pragma unroll
                for (int ni = 0; ni < 8; ni++)
                    mma_tf32(acc[mi][ni], af, bf[ni]);
            }
        }
    };

    ldreg(0);
    convst(0);
    __syncthreads();

    const int NCH = (DD / NSPLIT) / 16;   // 32
#pragma unroll 1
    for (int c = 0; c < NCH; c++) {
        if (c + 1 < NCH) ldreg(c + 1);
        compute(c & 1);
        if (c + 1 < NCH) convst((c + 1) & 1);
        __syncthreads();
    }

    float* tp = g_tp + (size_t)split * NN * ER;
#pragma unroll
    for (int mi = 0; mi < 4; mi++) {
        int ra2 = rowBase + wm * 64 + mi * 16 + gid;
#pragma unroll
        for (int half = 0; half < 2; half++) {
            int row = ra2 + half * 8;
#pragma unroll
            for (int ni = 0; ni < 8; ni++) {
                int col = wn * 64 + ni * 8 + tig * 2;
                float2 v;
                v.x = acc[mi][ni][half * 2 + 0];
                v.y = acc[mi][ni][half * 2 + 1];
                *(float2*)&tp[(size_t)row * ER + col] = v;
            }
        }
    }
}

// ---------------- kernel 4: reduce partials + apply expert gates (R13-proven) ----------------
__global__ void reduce_t_kernel()
{
    int i = blockIdx.x * blockDim.x + threadIdx.x;   // float4 index
    const int total = NN * ER / 4;
    if (i >= total) return;
    int row = (i * 4) / ER;
    int col = (i * 4) % ER;
    float4 s = make_float4(0.f, 0.f, 0.f, 0.f);
#pragma unroll
    for (int p = 0; p < NSPLIT; p++) {
        float4 v = ((const float4*)g_tp)[(size_t)p * total + i];
        s.x += v.x; s.y += v.y; s.z += v.z; s.w += v.w;
    }
    float g = g_gates[row * GG + 1 + (col >> 4)];
    s.x *= g; s.y *= g; s.z *= g; s.w *= g;
    ((float4*)g_t)[i] = s;
}

// ---------------- kernel 5: main tf32 GEMM — BK=32, 3-stage cp.async ----------------
// acc = x@W (128 chunks of K=32), then acc *= g0, then acc += t'@B_flat (4 chunks),
// epilogue: out = acc + g0*bias.
// BM=BN=128, BK=32; 4 warps (2x2), warp tile 64x64; 128 threads; 2 CTAs/SM.
// Raw fp32 tiles in 3-stage dynamic smem via cp.async; tf32 cvt at fragment load.
#define SA 36                              // A stride in u32 (32 + pad4): banks 4*gid+tig distinct
#define NC0 128  // chunks in base GEMM (4096/32)
#define NC  132  // + 4 lora chunks (128/32)
#define NSTG 3
#define A_U32 (128 * SA)                   // 4608 u32 per A stage
#define B_U32 (32 * SB)                    // 4352 u32 per B stage
#define SMEM_BYTES (NSTG * (A_U32 + B_U32) * 4)   // 107520 B

__global__ void __launch_bounds__(128, 2) mma_fused_kernel(const float* __restrict__ x,
                                                           const float* __restrict__ W,
                                                           const float* __restrict__ bias,
                                                           const float* __restrict__ loraB,
                                                           float* __restrict__ out)
{
    extern __shared__ __align__(16) uint32_t dsm[];
    uint32_t* Abase = dsm;                       // A stage s at +s*A_U32, row r at +r*SA
    uint32_t* Bbase = dsm + NSTG * A_U32;        // B stage s at +s*B_U32, k-row kr at +kr*SB

    int tid  = threadIdx.x;
    int wid  = tid >> 5;
    int lane = tid & 31;
    int gid  = lane >> 2;   // 0..7
    int tig  = lane & 3;    // 0..3
    int wm = wid >> 1;      // 0..1 (m offset *64)
    int wn = wid & 1;       // 0..1 (n offset *64)
    int rowBase = blockIdx.y * 128;
    int colBase = blockIdx.x * 128;

    float acc[4][8][4];
#pragma unroll
    for (int mi = 0; mi < 4; mi++)
#pragma unroll
        for (int ni = 0; ni < 8; ni++)
#pragma unroll
            for (int q = 0; q < 4; q++) acc[mi][ni][q] = 0.f;

    // per-thread copy slots (128 threads), BK=32:
    // A tile (128x32 fp32 = 1024 float4): slot j: row = (tid>>3)+16j, q = tid&7
    // B tile (32x128 fp32 = 1024 float4): slot j: kr  = (tid>>5)+4j,  q = tid&31
    int arow = tid >> 3, aq = tid & 7;
    int bkr  = tid >> 5, bq = tid & 31;

    uint32_t a_dst0 = smem_u32(&Abase[(size_t)arow * SA + aq * 4]);
    uint32_t b_dst0 = smem_u32(&Bbase[(size_t)bkr * SB + bq * 4]);

    auto issue = [&](int c) {
        const float *Asrc, *Bsrc;
        int Kp, k0;
        if (c < NC0) { Asrc = x;   Bsrc = W;     Kp = DD; k0 = c * 32; }
        else         { Asrc = g_t; Bsrc = loraB; Kp = ER; k0 = (c - NC0) * 32; }
        int s = c % NSTG;
        uint32_t ad = a_dst0 + (uint32_t)s * (A_U32 * 4);
        uint32_t bd = b_dst0 + (uint32_t)s * (B_U32 * 4);
#pragma unroll
        for (int j = 0; j < 8; j++) {
            cp16(ad + (uint32_t)(16 * j) * (SA * 4),
                 &Asrc[(size_t)(rowBase + arow + 16 * j) * Kp + k0 + aq * 4]);
            cp16(bd + (uint32_t)(4 * j) * (SB * 4),
                 &Bsrc[(size_t)(k0 + bkr + 4 * j) * OO + colBase + bq * 4]);
        }
        cp_commit();
    };

    auto compute = [&](int buf) {
        const uint32_t* Ab = Abase + (size_t)buf * A_U32;
        const uint32_t* Bb = Bbase + (size_t)buf * B_U32;
#pragma unroll
        for (int s = 0; s < 4; s++) {
            int k0 = s * 8 + tig;
            uint32_t bf[8][2];
#pragma unroll
            for (int ni = 0; ni < 8; ni++) {
                int n = wn * 64 + ni * 8 + gid;
                bf[ni][0] = to_tf32(__uint_as_float(Bb[(size_t)k0 * SB + n]));
                bf[ni][1] = to_tf32(__uint_as_float(Bb[(size_t)(k0 + 4) * SB + n]));
            }
#pragma unroll
            for (int mi = 0; mi < 4; mi++) {
                int r = wm * 64 + mi * 16 + gid;
                uint32_t af[4];
                af[0] = to_tf32(__uint_as_float(Ab[(size_t)r * SA + k0]));
                af[1] = to_tf32(__uint_as_float(Ab[(size_t)(r + 8) * SA + k0]));
                af[2] = to_tf32(__uint_as_float(Ab[(size_t)r * SA + k0 + 4]));
                af[3] = to_tf32(__uint_as_float(Ab[(size_t)(r + 8) * SA + k0 + 4]));
#pragma unroll
                for (int ni = 0; ni < 8; ni++)
                    mma_tf32(acc[mi][ni], af, bf[ni]);
            }
        }
    };

    // prologue: fill 2 stages
    issue(0);
    issue(1);

#pragma unroll 1
    for (int c = 0; c < NC; c++) {
        cp_wait1();            // outstanding {c, c+1}; <=1 left -> group c complete
        __syncthreads();       // stage c visible; compute(c-1) done by all warps
        if (c == NC0) {
            // base GEMM done: scale accumulators by base gate g0
#pragma unroll
            for (int mi = 0; mi < 4; mi++) {
                int rg = rowBase + wm * 64 + mi * 16 + gid;
                float g0a = g_gates[rg * GG];
                float g0b = g_gates[(rg + 8) * GG];
#pragma unroll
                for (int ni = 0; ni < 8; ni++) {
                    acc[mi][ni][0] *= g0a;
                    acc[mi][ni][1] *= g0a;
                    acc[mi][ni][2] *= g0b;
                    acc[mi][ni][3] *= g0b;
                }
            }
        }
        compute(c % NSTG);
        if (c + 2 < NC) issue(c + 2);   // writes stage (c-1)%3: readers fenced above
    }

    // ----- epilogue: out = acc + g0 * bias -----
#pragma unroll
    for (int mi = 0; mi < 4; mi++) {
        int ra2 = rowBase + wm * 64 + mi * 16 + gid;
#pragma unroll
        for (int half = 0; half < 2; half++) {
            int row = ra2 + half * 8;
            float g0 = g_gates[row * GG];
#pragma unroll
            for (int ni = 0; ni < 8; ni++) {
                int col = colBase + wn * 64 + ni * 8 + tig * 2;
                float2 v;
                v.x = acc[mi][ni][half * 2 + 0] + g0 * bias[col];
                v.y = acc[mi][ni][half * 2 + 1] + g0 * bias[col + 1];
                *(float2*)&out[(size_t)row * OO + col] = v;
            }
        }
    }
}

// ---------------- launcher ----------------
extern "C" void kernel_launch(void* const* d_in, const int* in_sizes, int n_in,
                              void* d_out, int out_size)
{
    const float* x      = (const float*)d_in[0];
    const float* W      = (const float*)d_in[1];
    const float* bias   = (const float*)d_in[2];
    const float* loraA  = (const float*)d_in[3];
    const float* loraB  = (const float*)d_in[4];
    const float* gw     = (const float*)d_in[5];
    // d_in[6] = bvv (unused by the reference computation)
    float* out = (float*)d_out;

    cudaFuncSetAttribute(mma_fused_kernel,
                         cudaFuncAttributeMaxDynamicSharedMemorySize, SMEM_BYTES);

    transpose_A_kernel<<<512, 256>>>(loraA);
    gate_kernel<<<NN / 8, 256>>>(x, gw);
    loraA_tc_kernel<<<dim3(NSPLIT, NN / 128), 128>>>(x);
    reduce_t_kernel<<<NN * ER / 4 / 256, 256>>>();
    mma_fused_kernel<<<dim3(OO / 128, NN / 128), 128, SMEM_BYTES>>>(x, W, bias, loraB, out);
}

// round 16
// speedup vs baseline: 1.0147x; 1.0147x over previous
#include <cuda_runtime.h>
#include <cuda_bf16.h>
#include <math.h>
#include <stdint.h>

// ---------------- problem constants ----------------
#define NN 4096
#define DD 4096
#define OO 4096
#define EE 8
#define RR 16
#define ER 128      // E*R
#define GG 9        // E+1
#define NSPLIT 8    // K-splits for the loraA tensor-core GEMM

// ---------------- device scratch ----------------
__device__ float g_gates[NN * GG];              // softmax gates per row
__device__ float g_t[NN * ER];                  // gated LoRA intermediate t'
__device__ float g_At[DD * ER];                 // lora_A transposed to [d][e*16+r]
__device__ float g_tp[NSPLIT * NN * ER];        // K-split partials of x@At (16 MB)

// ---------------- tf32 / async helpers (sm_80+ baseline ISA) ----------------
__device__ __forceinline__ uint32_t to_tf32(float v) {
    uint32_t r;
    asm("cvt.rna.tf32.f32 %0, %1;" : "=r"(r) : "f"(v));
    return r;
}
__device__ __forceinline__ void mma_tf32(float* c, const uint32_t* a, const uint32_t* b) {
    asm volatile(
        "mma.sync.aligned.m16n8k8.row.col.f32.tf32.tf32.f32 "
        "{%0,%1,%2,%3}, {%4,%5,%6,%7}, {%8,%9}, {%0,%1,%2,%3};"
        : "+f"(c[0]), "+f"(c[1]), "+f"(c[2]), "+f"(c[3])
        : "r"(a[0]), "r"(a[1]), "r"(a[2]), "r"(a[3]), "r"(b[0]), "r"(b[1]));
}
__device__ __forceinline__ uint32_t smem_u32(const void* p) {
    uint32_t a;
    asm("{ .reg .u64 t; cvta.to.shared.u64 t, %1; cvt.u32.u64 %0, t; }" : "=r"(a) : "l"(p));
    return a;
}
__device__ __forceinline__ void cp16(uint32_t smem, const void* gmem) {
    asm volatile("cp.async.cg.shared.global [%0], [%1], 16;" :: "r"(smem), "l"(gmem) : "memory");
}
__device__ __forceinline__ void cp_commit() {
    asm volatile("cp.async.commit_group;" ::: "memory");
}
__device__ __forceinline__ void cp_wait1() {
    asm volatile("cp.async.wait_group 1;" ::: "memory");
}

// ---------------- kernel 0: zero the output (atomic accumulation base) ----------------
__global__ void zero_out_kernel(float4* __restrict__ out)
{
    int i = blockIdx.x * blockDim.x + threadIdx.x;
    out[i] = make_float4(0.f, 0.f, 0.f, 0.f);
}

// ---------------- kernel 1: gate logits + top2 + softmax (R1-proven) ----------------
__global__ void gate_kernel(const float* __restrict__ x,
                            const float* __restrict__ gw)
{
    int warp = (blockIdx.x * blockDim.x + threadIdx.x) >> 5;
    int lane = threadIdx.x & 31;
    if (warp >= NN) return;
    const float* xr = x + (size_t)warp * DD;

    float acc[GG];
#pragma unroll
    for (int c = 0; c < GG; c++) acc[c] = 0.f;

    for (int d = lane; d < DD; d += 32) {
        float xv = xr[d];
#pragma unroll
        for (int c = 0; c < GG; c++)
            acc[c] += xv * gw[c * DD + d];
    }
#pragma unroll
    for (int c = 0; c < GG; c++) {
#pragma unroll
        for (int off = 16; off > 0; off >>= 1)
            acc[c] += __shfl_xor_sync(0xFFFFFFFFu, acc[c], off);
    }

    if (lane == 0) {
        float m1 = -INFINITY, m2 = -INFINITY;
        int i1 = -1, i2 = -1;
#pragma unroll
        for (int c = 1; c < GG; c++) {
            float v = acc[c];
            if (v > m1) { m2 = m1; i2 = i1; m1 = v; i1 = c; }
            else if (v > m2) { m2 = v; i2 = c; }
        }
        float vals[GG];
        vals[0] = acc[0];
#pragma unroll
        for (int c = 1; c < GG; c++)
            vals[c] = (c == i1 || c == i2) ? acc[c] : 0.0f;

        float mx = vals[0];
#pragma unroll
        for (int c = 1; c < GG; c++) mx = fmaxf(mx, vals[c]);
        float s = 0.f;
        float e[GG];
#pragma unroll
        for (int c = 0; c < GG; c++) { e[c] = __expf(vals[c] - mx); s += e[c]; }
        float inv = 1.0f / s;
#pragma unroll
        for (int c = 0; c < GG; c++)
            g_gates[warp * GG + c] = e[c] * inv;
    }
}

// ---------------- kernel 2: transpose lora_A -> [d][e*16+r] (R1-proven) ----------------
__global__ void transpose_A_kernel(const float* __restrict__ loraA)
{
    int total = EE * DD * RR;
    for (int i = blockIdx.x * blockDim.x + threadIdx.x; i < total;
         i += gridDim.x * blockDim.x) {
        int e = i / (DD * RR);
        int d = (i / RR) % DD;
        int r = i % RR;
        g_At[d * ER + e * RR + r] = loraA[i];
    }
}

// ---------------- shared geometry (R11-proven) ----------------
#define SA16 20  // loraA kernel: A stride (16 + pad4)
#define SB 136   // B smem stride in u32 (128 + pad8): frag banks 8*tig+gid distinct

// ---------------- kernel 3: loraA tensor-core GEMM, K-split (R13-proven, verbatim) ----------------
__global__ void __launch_bounds__(128, 2) loraA_tc_kernel(const float* __restrict__ x)
{
    __shared__ __align__(16) uint32_t At2[2][128][SA16];
    __shared__ __align__(16) uint32_t Bt2[2][16][SB];

    int tid  = threadIdx.x;
    int wid  = tid >> 5;
    int lane = tid & 31;
    int gid  = lane >> 2;
    int tig  = lane & 3;
    int wm = wid >> 1;
    int wn = wid & 1;
    int split   = blockIdx.x;               // 0..7
    int rowBase = blockIdx.y * 128;
    int kBase   = split * (DD / NSPLIT);    // 512 per split

    float acc[4][8][4];
#pragma unroll
    for (int mi = 0; mi < 4; mi++)
#pragma unroll
        for (int ni = 0; ni < 8; ni++)
#pragma unroll
            for (int q = 0; q < 4; q++) acc[mi][ni][q] = 0.f;

    int arow = tid >> 2, aq = tid & 3;
    int bkr  = tid >> 5, bq = tid & 31;

    float4 ra[4], rb[4];

    auto ldreg = [&](int c) {
        int k0 = kBase + c * 16;
#pragma unroll
        for (int j = 0; j < 4; j++) {
            ra[j] = *(const float4*)&x[(size_t)(rowBase + arow + 32 * j) * DD + k0 + aq * 4];
            rb[j] = *(const float4*)&g_At[(size_t)(k0 + bkr + 4 * j) * ER + bq * 4];
        }
    };
    auto convst = [&](int s) {
#pragma unroll
        for (int j = 0; j < 4; j++) {
            *(uint4*)&At2[s][arow + 32 * j][aq * 4] =
                make_uint4(to_tf32(ra[j].x), to_tf32(ra[j].y), to_tf32(ra[j].z), to_tf32(ra[j].w));
            *(uint4*)&Bt2[s][bkr + 4 * j][bq * 4] =
                make_uint4(to_tf32(rb[j].x), to_tf32(rb[j].y), to_tf32(rb[j].z), to_tf32(rb[j].w));
        }
    };
    auto compute = [&](int buf) {
#pragma unroll
        for (int s = 0; s < 2; s++) {
            int k0 = s * 8 + tig;
            uint32_t bf[8][2];
#pragma unroll
            for (int ni = 0; ni < 8; ni++) {
                int n = wn * 64 + ni * 8 + gid;
                bf[ni][0] = Bt2[buf][k0][n];
                bf[ni][1] = Bt2[buf][k0 + 4][n];
            }
#pragma unroll
            for (int mi = 0; mi < 4; mi++) {
                int r = wm * 64 + mi * 16 + gid;
                uint32_t af[4];
                af[0] = At2[buf][r][k0];
                af[1] = At2[buf][r + 8][k0];
                af[2] = At2[buf][r][k0 + 4];
                af[3] = At2[buf][r + 8][k0 + 4];
#pragma unroll
                for (int ni = 0; ni < 8; ni++)
                    mma_tf32(acc[mi][ni], af, bf[ni]);
            }
        }
    };

    ldreg(0);
    convst(0);
    __syncthreads();

    const int NCH = (DD / NSPLIT) / 16;   // 32
#pragma unroll 1
    for (int c = 0; c < NCH; c++) {
        if (c + 1 < NCH) ldreg(c + 1);
        compute(c & 1);
        if (c + 1 < NCH) convst((c + 1) & 1);
        __syncthreads();
    }

    float* tp = g_tp + (size_t)split * NN * ER;
#pragma unroll
    for (int mi = 0; mi < 4; mi++) {
        int ra2 = rowBase + wm * 64 + mi * 16 + gid;
#pragma unroll
        for (int half = 0; half < 2; half++) {
            int row = ra2 + half * 8;
#pragma unroll
            for (int ni = 0; ni < 8; ni++) {
                int col = wn * 64 + ni * 8 + tig * 2;
                float2 v;
                v.x = acc[mi][ni][half * 2 + 0];
                v.y = acc[mi][ni][half * 2 + 1];
                *(float2*)&tp[(size_t)row * ER + col] = v;
            }
        }
    }
}

// ---------------- kernel 4: reduce partials + apply expert gates (R13-proven) ----------------
__global__ void reduce_t_kernel()
{
    int i = blockIdx.x * blockDim.x + threadIdx.x;   // float4 index
    const int total = NN * ER / 4;
    if (i >= total) return;
    int row = (i * 4) / ER;
    int col = (i * 4) % ER;
    float4 s = make_float4(0.f, 0.f, 0.f, 0.f);
#pragma unroll
    for (int p = 0; p < NSPLIT; p++) {
        float4 v = ((const float4*)g_tp)[(size_t)p * total + i];
        s.x += v.x; s.y += v.y; s.z += v.z; s.w += v.w;
    }
    float g = g_gates[row * GG + 1 + (col >> 4)];
    s.x *= g; s.y *= g; s.z *= g; s.w *= g;
    ((float4*)g_t)[i] = s;
}

// ---------------- kernel 5: main tf32 GEMM — split-K2, BK=32, 3-stage cp.async ----------------
// z=0: P1 = x[:, 0:2048] @ W-half      -> atomicAdd(out, g0*P1)
// z=1: P2 = x[:, 2048:4096] @ W-half; then acc*=g0; then += t'@B_flat (4 chunks)
//      -> atomicAdd(out, acc + g0*bias)
// Sum = g0*(x@W + b) + t'@B. Exactly 2 fp32 addends/address (commutative -> deterministic).
// BM=BN=128, BK=32; 4 warps (2x2), warp tile 64x64; 128 threads; 2 CTAs/SM.
#define SA 36                              // A stride in u32 (32 + pad4): banks 4*gid+tig distinct
#define KHALF 2048
#define NCH0 64   // chunks of x@W per split (2048/32)
#define NSTG 3
#define A_U32 (128 * SA)                   // 4608 u32 per A stage
#define B_U32 (32 * SB)                    // 4352 u32 per B stage
#define SMEM_BYTES (NSTG * (A_U32 + B_U32) * 4)   // 107520 B

__global__ void __launch_bounds__(128, 2) mma_fused_kernel(const float* __restrict__ x,
                                                           const float* __restrict__ W,
                                                           const float* __restrict__ bias,
                                                           const float* __restrict__ loraB,
                                                           float* __restrict__ out)
{
    extern __shared__ __align__(16) uint32_t dsm[];
    uint32_t* Abase = dsm;                       // A stage s at +s*A_U32, row r at +r*SA
    uint32_t* Bbase = dsm + NSTG * A_U32;        // B stage s at +s*B_U32, k-row kr at +kr*SB

    int tid  = threadIdx.x;
    int wid  = tid >> 5;
    int lane = tid & 31;
    int gid  = lane >> 2;   // 0..7
    int tig  = lane & 3;    // 0..3
    int wm = wid >> 1;      // 0..1 (m offset *64)
    int wn = wid & 1;       // 0..1 (n offset *64)
    int rowBase = blockIdx.y * 128;
    int colBase = blockIdx.x * 128;
    int zsplit  = blockIdx.z;                    // 0 or 1
    const int NCs = zsplit ? (NCH0 + ER / 32) : NCH0;   // 68 : 64

    float acc[4][8][4];
#pragma unroll
    for (int mi = 0; mi < 4; mi++)
#pragma unroll
        for (int ni = 0; ni < 8; ni++)
#pragma unroll
            for (int q = 0; q < 4; q++) acc[mi][ni][q] = 0.f;

    // per-thread copy slots (128 threads), BK=32:
    int arow = tid >> 3, aq = tid & 7;
    int bkr  = tid >> 5, bq = tid & 31;

    uint32_t a_dst0 = smem_u32(&Abase[(size_t)arow * SA + aq * 4]);
    uint32_t b_dst0 = smem_u32(&Bbase[(size_t)bkr * SB + bq * 4]);

    auto issue = [&](int c) {
        const float *Asrc, *Bsrc;
        int Kp, k0;
        if (c < NCH0) {
            Asrc = x; Bsrc = W; Kp = DD;
            k0 = zsplit * KHALF + c * 32;
        } else {
            Asrc = g_t; Bsrc = loraB; Kp = ER;
            k0 = (c - NCH0) * 32;
        }
        int s = c % NSTG;
        uint32_t ad = a_dst0 + (uint32_t)s * (A_U32 * 4);
        uint32_t bd = b_dst0 + (uint32_t)s * (B_U32 * 4);
#pragma unroll
        for (int j = 0; j < 8; j++) {
            cp16(ad + (uint32_t)(16 * j) * (SA * 4),
                 &Asrc[(size_t)(rowBase + arow + 16 * j) * Kp + k0 + aq * 4]);
            cp16(bd + (uint32_t)(4 * j) * (SB * 4),
                 &Bsrc[(size_t)(k0 + bkr + 4 * j) * OO + colBase + bq * 4]);
        }
        cp_commit();
    };

    auto compute = [&](int buf) {
        const uint32_t* Ab = Abase + (size_t)buf * A_U32;
        const uint32_t* Bb = Bbase + (size_t)buf * B_U32;
#pragma unroll
        for (int s = 0; s < 4; s++) {
            int k0 = s * 8 + tig;
            uint32_t bf[8][2];
#pragma unroll
            for (int ni = 0; ni < 8; ni++) {
                int n = wn * 64 + ni * 8 + gid;
                bf[ni][0] = to_tf32(__uint_as_float(Bb[(size_t)k0 * SB + n]));
                bf[ni][1] = to_tf32(__uint_as_float(Bb[(size_t)(k0 + 4) * SB + n]));
            }
#pragma unroll
            for (int mi = 0; mi < 4; mi++) {
                int r = wm * 64 + mi * 16 + gid;
                uint32_t af[4];
                af[0] = to_tf32(__uint_as_float(Ab[(size_t)r * SA + k0]));
                af[1] = to_tf32(__uint_as_float(Ab[(size_t)(r + 8) * SA + k0]));
                af[2] = to_tf32(__uint_as_float(Ab[(size_t)r * SA + k0 + 4]));
                af[3] = to_tf32(__uint_as_float(Ab[(size_t)(r + 8) * SA + k0 + 4]));
#pragma unroll
                for (int ni = 0; ni < 8; ni++)
                    mma_tf32(acc[mi][ni], af, bf[ni]);
            }
        }
    };

    // prologue: fill 2 stages
    issue(0);
    issue(1);

#pragma unroll 1
    for (int c = 0; c < NCs; c++) {
        cp_wait1();            // outstanding {c, c+1}; <=1 left -> group c complete
        __syncthreads();       // stage c visible; compute(c-1) done by all warps
        if (zsplit == 1 && c == NCH0) {
            // base half done: scale accumulators by base gate g0 before lora chunks
#pragma unroll
            for (int mi = 0; mi < 4; mi++) {
                int rg = rowBase + wm * 64 + mi * 16 + gid;
                float g0a = g_gates[rg * GG];
                float g0b = g_gates[(rg + 8) * GG];
#pragma unroll
                for (int ni = 0; ni < 8; ni++) {
                    acc[mi][ni][0] *= g0a;
                    acc[mi][ni][1] *= g0a;
                    acc[mi][ni][2] *= g0b;
                    acc[mi][ni][3] *= g0b;
                }
            }
        }
        compute(c % NSTG);
        if (c + 2 < NCs) issue(c + 2);   // writes stage (c-1)%3: readers fenced above
    }

    // ----- epilogue: atomic-accumulate this split's contribution -----
#pragma unroll
    for (int mi = 0; mi < 4; mi++) {
        int ra2 = rowBase + wm * 64 + mi * 16 + gid;
#pragma unroll
        for (int half = 0; half < 2; half++) {
            int row = ra2 + half * 8;
            float g0 = g_gates[row * GG];
#pragma unroll
            for (int ni = 0; ni < 8; ni++) {
                int col = colBase + wn * 64 + ni * 8 + tig * 2;
                float vx, vy;
                if (zsplit == 0) {
                    vx = g0 * acc[mi][ni][half * 2 + 0];
                    vy = g0 * acc[mi][ni][half * 2 + 1];
                } else {
                    vx = acc[mi][ni][half * 2 + 0] + g0 * bias[col];
                    vy = acc[mi][ni][half * 2 + 1] + g0 * bias[col + 1];
                }
                atomicAdd(&out[(size_t)row * OO + col], vx);
                atomicAdd(&out[(size_t)row * OO + col + 1], vy);
            }
        }
    }
}

// ---------------- launcher ----------------
extern "C" void kernel_launch(void* const* d_in, const int* in_sizes, int n_in,
                              void* d_out, int out_size)
{
    const float* x      = (const float*)d_in[0];
    const float* W      = (const float*)d_in[1];
    const float* bias   = (const float*)d_in[2];
    const float* loraA  = (const float*)d_in[3];
    const float* loraB  = (const float*)d_in[4];
    const float* gw     = (const float*)d_in[5];
    // d_in[6] = bvv (unused by the reference computation)
    float* out = (float*)d_out;

    cudaFuncSetAttribute(mma_fused_kernel,
                         cudaFuncAttributeMaxDynamicSharedMemorySize, SMEM_BYTES);

    zero_out_kernel<<<NN * OO / 4 / 256, 256>>>((float4*)out);
    transpose_A_kernel<<<512, 256>>>(loraA);
    gate_kernel<<<NN / 8, 256>>>(x, gw);
    loraA_tc_kernel<<<dim3(NSPLIT, NN / 128), 128>>>(x);
    reduce_t_kernel<<<NN * ER / 4 / 256, 256>>>();
    mma_fused_kernel<<<dim3(OO / 128, NN / 128, 2), 128, SMEM_BYTES>>>(x, W, bias, loraB, out);
}

// round 17
// speedup vs baseline: 1.0206x; 1.0058x over previous
#include <cuda_runtime.h>
#include <cuda_bf16.h>
#include <math.h>
#include <stdint.h>

// ---------------- problem constants ----------------
#define NN 4096
#define DD 4096
#define OO 4096
#define EE 8
#define RR 16
#define ER 128      // E*R
#define GG 9        // E+1
#define NSPLIT 8    // K-splits for the loraA tensor-core GEMM

// ---------------- device scratch ----------------
__device__ float g_gates[NN * GG];              // softmax gates per row
__device__ float g_t[NN * ER];                  // gated LoRA intermediate t'
__device__ uint32_t g_At32[DD * ER];            // lora_A transposed + tf32-converted
__device__ float g_tp[NSPLIT * NN * ER];        // K-split partials of x@At (16 MB)
__device__ uint32_t g_W32[(size_t)DD * OO];     // W pre-converted to tf32 bits (64 MB)
__device__ uint32_t g_B32[ER * OO];             // loraB pre-converted to tf32 bits (2 MB)

// ---------------- tf32 / async helpers (sm_80+ baseline ISA) ----------------
__device__ __forceinline__ uint32_t to_tf32(float v) {
    uint32_t r;
    asm("cvt.rna.tf32.f32 %0, %1;" : "=r"(r) : "f"(v));
    return r;
}
__device__ __forceinline__ void mma_tf32(float* c, const uint32_t* a, const uint32_t* b) {
    asm volatile(
        "mma.sync.aligned.m16n8k8.row.col.f32.tf32.tf32.f32 "
        "{%0,%1,%2,%3}, {%4,%5,%6,%7}, {%8,%9}, {%0,%1,%2,%3};"
        : "+f"(c[0]), "+f"(c[1]), "+f"(c[2]), "+f"(c[3])
        : "r"(a[0]), "r"(a[1]), "r"(a[2]), "r"(a[3]), "r"(b[0]), "r"(b[1]));
}
__device__ __forceinline__ uint32_t smem_u32(const void* p) {
    uint32_t a;
    asm("{ .reg .u64 t; cvta.to.shared.u64 t, %1; cvt.u32.u64 %0, t; }" : "=r"(a) : "l"(p));
    return a;
}
__device__ __forceinline__ void cp16(uint32_t smem, const void* gmem) {
    asm volatile("cp.async.cg.shared.global [%0], [%1], 16;" :: "r"(smem), "l"(gmem) : "memory");
}
__device__ __forceinline__ void cp_commit() {
    asm volatile("cp.async.commit_group;" ::: "memory");
}
__device__ __forceinline__ void cp_wait1() {
    asm volatile("cp.async.wait_group 1;" ::: "memory");
}

// ---------------- kernel 0a: zero the output (atomic accumulation base) ----------------
__global__ void zero_out_kernel(float4* __restrict__ out)
{
    int i = blockIdx.x * blockDim.x + threadIdx.x;
    out[i] = make_float4(0.f, 0.f, 0.f, 0.f);
}

// ---------------- kernel 0b: pre-convert fp32 matrix -> tf32 bits ----------------
__global__ void conv_tf32_kernel(const float4* __restrict__ src,
                                 uint4* __restrict__ dst, int n4)
{
    for (int i = blockIdx.x * blockDim.x + threadIdx.x; i < n4;
         i += gridDim.x * blockDim.x) {
        float4 v = src[i];
        dst[i] = make_uint4(to_tf32(v.x), to_tf32(v.y), to_tf32(v.z), to_tf32(v.w));
    }
}

// ---------------- kernel 1: gate logits + top2 + softmax (float4-vectorized) ----------------
__global__ void gate_kernel(const float* __restrict__ x,
                            const float* __restrict__ gw)
{
    int warp = (blockIdx.x * blockDim.x + threadIdx.x) >> 5;
    int lane = threadIdx.x & 31;
    if (warp >= NN) return;
    const float4* xr = (const float4*)(x + (size_t)warp * DD);

    float acc[GG];
#pragma unroll
    for (int c = 0; c < GG; c++) acc[c] = 0.f;

    for (int d4 = lane; d4 < DD / 4; d4 += 32) {
        float4 xv = xr[d4];
#pragma unroll
        for (int c = 0; c < GG; c++) {
            float4 gv = ((const float4*)(gw + (size_t)c * DD))[d4];
            acc[c] += xv.x * gv.x + xv.y * gv.y + xv.z * gv.z + xv.w * gv.w;
        }
    }
#pragma unroll
    for (int c = 0; c < GG; c++) {
#pragma unroll
        for (int off = 16; off > 0; off >>= 1)
            acc[c] += __shfl_xor_sync(0xFFFFFFFFu, acc[c], off);
    }

    if (lane == 0) {
        float m1 = -INFINITY, m2 = -INFINITY;
        int i1 = -1, i2 = -1;
#pragma unroll
        for (int c = 1; c < GG; c++) {
            float v = acc[c];
            if (v > m1) { m2 = m1; i2 = i1; m1 = v; i1 = c; }
            else if (v > m2) { m2 = v; i2 = c; }
        }
        float vals[GG];
        vals[0] = acc[0];
#pragma unroll
        for (int c = 1; c < GG; c++)
            vals[c] = (c == i1 || c == i2) ? acc[c] : 0.0f;

        float mx = vals[0];
#pragma unroll
        for (int c = 1; c < GG; c++) mx = fmaxf(mx, vals[c]);
        float s = 0.f;
        float e[GG];
#pragma unroll
        for (int c = 0; c < GG; c++) { e[c] = __expf(vals[c] - mx); s += e[c]; }
        float inv = 1.0f / s;
#pragma unroll
        for (int c = 0; c < GG; c++)
            g_gates[warp * GG + c] = e[c] * inv;
    }
}

// ---------------- kernel 2: transpose lora_A -> [d][e*16+r], tf32-converted ----------------
__global__ void transpose_A_kernel(const float* __restrict__ loraA)
{
    int total = EE * DD * RR;
    for (int i = blockIdx.x * blockDim.x + threadIdx.x; i < total;
         i += gridDim.x * blockDim.x) {
        int e = i / (DD * RR);
        int d = (i / RR) % DD;
        int r = i % RR;
        g_At32[d * ER + e * RR + r] = to_tf32(loraA[i]);
    }
}

// ---------------- shared geometry (R11-proven) ----------------
#define SA16 20  // loraA kernel: A stride (16 + pad4)
#define SB 136   // B smem stride in u32 (128 + pad8): frag banks 8*tig+gid distinct

// ---------------- kernel 3: loraA tensor-core GEMM, K-split ----------------
// B operand (g_At32) is pre-converted tf32; A (x) converted at tile store.
__global__ void __launch_bounds__(128, 2) loraA_tc_kernel(const float* __restrict__ x)
{
    __shared__ __align__(16) uint32_t At2[2][128][SA16];
    __shared__ __align__(16) uint32_t Bt2[2][16][SB];

    int tid  = threadIdx.x;
    int wid  = tid >> 5;
    int lane = tid & 31;
    int gid  = lane >> 2;
    int tig  = lane & 3;
    int wm = wid >> 1;
    int wn = wid & 1;
    int split   = blockIdx.x;               // 0..7
    int rowBase = blockIdx.y * 128;
    int kBase   = split * (DD / NSPLIT);    // 512 per split

    float acc[4][8][4];
#pragma unroll
    for (int mi = 0; mi < 4; mi++)
#pragma unroll
        for (int ni = 0; ni < 8; ni++)
#pragma unroll
            for (int q = 0; q < 4; q++) acc[mi][ni][q] = 0.f;

    int arow = tid >> 2, aq = tid & 3;
    int bkr  = tid >> 5, bq = tid & 31;

    float4 ra[4];
    uint4  rb[4];

    auto ldreg = [&](int c) {
        int k0 = kBase + c * 16;
#pragma unroll
        for (int j = 0; j < 4; j++) {
            ra[j] = *(const float4*)&x[(size_t)(rowBase + arow + 32 * j) * DD + k0 + aq * 4];
            rb[j] = *(const uint4*)&g_At32[(size_t)(k0 + bkr + 4 * j) * ER + bq * 4];
        }
    };
    auto convst = [&](int s) {
#pragma unroll
        for (int j = 0; j < 4; j++) {
            *(uint4*)&At2[s][arow + 32 * j][aq * 4] =
                make_uint4(to_tf32(ra[j].x), to_tf32(ra[j].y), to_tf32(ra[j].z), to_tf32(ra[j].w));
            *(uint4*)&Bt2[s][bkr + 4 * j][bq * 4] = rb[j];
        }
    };
    auto compute = [&](int buf) {
#pragma unroll
        for (int s = 0; s < 2; s++) {
            int k0 = s * 8 + tig;
            uint32_t bf[8][2];
#pragma unroll
            for (int ni = 0; ni < 8; ni++) {
                int n = wn * 64 + ni * 8 + gid;
                bf[ni][0] = Bt2[buf][k0][n];
                bf[ni][1] = Bt2[buf][k0 + 4][n];
            }
#pragma unroll
            for (int mi = 0; mi < 4; mi++) {
                int r = wm * 64 + mi * 16 + gid;
                uint32_t af[4];
                af[0] = At2[buf][r][k0];
                af[1] = At2[buf][r + 8][k0];
                af[2] = At2[buf][r][k0 + 4];
                af[3] = At2[buf][r + 8][k0 + 4];
#pragma unroll
                for (int ni = 0; ni < 8; ni++)
                    mma_tf32(acc[mi][ni], af, bf[ni]);
            }
        }
    };

    ldreg(0);
    convst(0);
    __syncthreads();

    const int NCH = (DD / NSPLIT) / 16;   // 32
#pragma unroll 1
    for (int c = 0; c < NCH; c++) {
        if (c + 1 < NCH) ldreg(c + 1);
        compute(c & 1);
        if (c + 1 < NCH) convst((c + 1) & 1);
        __syncthreads();
    }

    float* tp = g_tp + (size_t)split * NN * ER;
#pragma unroll
    for (int mi = 0; mi < 4; mi++) {
        int ra2 = rowBase + wm * 64 + mi * 16 + gid;
#pragma unroll
        for (int half = 0; half < 2; half++) {
            int row = ra2 + half * 8;
#pragma unroll
            for (int ni = 0; ni < 8; ni++) {
                int col = wn * 64 + ni * 8 + tig * 2;
                float2 v;
                v.x = acc[mi][ni][half * 2 + 0];
                v.y = acc[mi][ni][half * 2 + 1];
                *(float2*)&tp[(size_t)row * ER + col] = v;
            }
        }
    }
}

// ---------------- kernel 4: reduce partials + apply expert gates (R13-proven) ----------------
__global__ void reduce_t_kernel()
{
    int i = blockIdx.x * blockDim.x + threadIdx.x;   // float4 index
    const int total = NN * ER / 4;
    if (i >= total) return;
    int row = (i * 4) / ER;
    int col = (i * 4) % ER;
    float4 s = make_float4(0.f, 0.f, 0.f, 0.f);
#pragma unroll
    for (int p = 0; p < NSPLIT; p++) {
        float4 v = ((const float4*)g_tp)[(size_t)p * total + i];
        s.x += v.x; s.y += v.y; s.z += v.z; s.w += v.w;
    }
    float g = g_gates[row * GG + 1 + (col >> 4)];
    s.x *= g; s.y *= g; s.z *= g; s.w *= g;
    ((float4*)g_t)[i] = s;
}

// ---------------- kernel 5: main tf32 GEMM — split-K2, BK=32, 3-stage cp.async ----------------
// B operands (g_W32 / g_B32) are PRE-CONVERTED tf32: B fragments are plain LDS.
// A operands (x / g_t) stay fp32: cvt.rna at A-fragment load (16/thread-chunk).
// z=0: atomicAdd(out, g0*(x[:,0:2048]@W-half))
// z=1: acc = x[:,2048:4096]@W-half; acc*=g0; acc += t'@B; atomicAdd(out, acc + g0*bias)
#define SA 36                              // A stride in u32 (32 + pad4): banks 4*gid+tig distinct
#define KHALF 2048
#define NCH0 64   // chunks of x@W per split (2048/32)
#define NSTG 3
#define A_U32 (128 * SA)                   // 4608 u32 per A stage
#define B_U32 (32 * SB)                    // 4352 u32 per B stage
#define SMEM_BYTES (NSTG * (A_U32 + B_U32) * 4)   // 107520 B

__global__ void __launch_bounds__(128, 2) mma_fused_kernel(const float* __restrict__ x,
                                                           const float* __restrict__ bias,
                                                           float* __restrict__ out)
{
    extern __shared__ __align__(16) uint32_t dsm[];
    uint32_t* Abase = dsm;                       // A stage s at +s*A_U32, row r at +r*SA
    uint32_t* Bbase = dsm + NSTG * A_U32;        // B stage s at +s*B_U32, k-row kr at +kr*SB

    int tid  = threadIdx.x;
    int wid  = tid >> 5;
    int lane = tid & 31;
    int gid  = lane >> 2;   // 0..7
    int tig  = lane & 3;    // 0..3
    int wm = wid >> 1;      // 0..1 (m offset *64)
    int wn = wid & 1;       // 0..1 (n offset *64)
    int rowBase = blockIdx.y * 128;
    int colBase = blockIdx.x * 128;
    int zsplit  = blockIdx.z;                    // 0 or 1
    const int NCs = zsplit ? (NCH0 + ER / 32) : NCH0;   // 68 : 64

    float acc[4][8][4];
#pragma unroll
    for (int mi = 0; mi < 4; mi++)
#pragma unroll
        for (int ni = 0; ni < 8; ni++)
#pragma unroll
            for (int q = 0; q < 4; q++) acc[mi][ni][q] = 0.f;

    // per-thread copy slots (128 threads), BK=32:
    int arow = tid >> 3, aq = tid & 7;
    int bkr  = tid >> 5, bq = tid & 31;

    uint32_t a_dst0 = smem_u32(&Abase[(size_t)arow * SA + aq * 4]);
    uint32_t b_dst0 = smem_u32(&Bbase[(size_t)bkr * SB + bq * 4]);

    auto issue = [&](int c) {
        const float* Asrc;
        const uint32_t* Bsrc;
        int Kp, k0;
        if (c < NCH0) {
            Asrc = x; Bsrc = g_W32; Kp = DD;
            k0 = zsplit * KHALF + c * 32;
        } else {
            Asrc = g_t; Bsrc = g_B32; Kp = ER;
            k0 = (c - NCH0) * 32;
        }
        int s = c % NSTG;
        uint32_t ad = a_dst0 + (uint32_t)s * (A_U32 * 4);
        uint32_t bd = b_dst0 + (uint32_t)s * (B_U32 * 4);
#pragma unroll
        for (int j = 0; j < 8; j++) {
            cp16(ad + (uint32_t)(16 * j) * (SA * 4),
                 &Asrc[(size_t)(rowBase + arow + 16 * j) * Kp + k0 + aq * 4]);
            cp16(bd + (uint32_t)(4 * j) * (SB * 4),
                 &Bsrc[(size_t)(k0 + bkr + 4 * j) * OO + colBase + bq * 4]);
        }
        cp_commit();
    };

    auto compute = [&](int buf) {
        const uint32_t* Ab = Abase + (size_t)buf * A_U32;
        const uint32_t* Bb = Bbase + (size_t)buf * B_U32;
#pragma unroll
        for (int s = 0; s < 4; s++) {
            int k0 = s * 8 + tig;
            uint32_t bf[8][2];
#pragma unroll
            for (int ni = 0; ni < 8; ni++) {
                int n = wn * 64 + ni * 8 + gid;
                bf[ni][0] = Bb[(size_t)k0 * SB + n];           // pre-converted tf32
                bf[ni][1] = Bb[(size_t)(k0 + 4) * SB + n];
            }
#pragma unroll
            for (int mi = 0; mi < 4; mi++) {
                int r = wm * 64 + mi * 16 + gid;
                uint32_t af[4];
                af[0] = to_tf32(__uint_as_float(Ab[(size_t)r * SA + k0]));
                af[1] = to_tf32(__uint_as_float(Ab[(size_t)(r + 8) * SA + k0]));
                af[2] = to_tf32(__uint_as_float(Ab[(size_t)r * SA + k0 + 4]));
                af[3] = to_tf32(__uint_as_float(Ab[(size_t)(r + 8) * SA + k0 + 4]));
#pragma unroll
                for (int ni = 0; ni < 8; ni++)
                    mma_tf32(acc[mi][ni], af, bf[ni]);
            }
        }
    };

    // prologue: fill 2 stages
    issue(0);
    issue(1);

#pragma unroll 1
    for (int c = 0; c < NCs; c++) {
        cp_wait1();            // outstanding {c, c+1}; <=1 left -> group c complete
        __syncthreads();       // stage c visible; compute(c-1) done by all warps
        if (zsplit == 1 && c == NCH0) {
            // base half done: scale accumulators by base gate g0 before lora chunks
#pragma unroll
            for (int mi = 0; mi < 4; mi++) {
                int rg = rowBase + wm * 64 + mi * 16 + gid;
                float g0a = g_gates[rg * GG];
                float g0b = g_gates[(rg + 8) * GG];
#pragma unroll
                for (int ni = 0; ni < 8; ni++) {
                    acc[mi][ni][0] *= g0a;
                    acc[mi][ni][1] *= g0a;
                    acc[mi][ni][2] *= g0b;
                    acc[mi][ni][3] *= g0b;
                }
            }
        }
        compute(c % NSTG);
        if (c + 2 < NCs) issue(c + 2);   // writes stage (c-1)%3: readers fenced above
    }

    // ----- epilogue: atomic-accumulate this split's contribution -----
#pragma unroll
    for (int mi = 0; mi < 4; mi++) {
        int ra2 = rowBase + wm * 64 + mi * 16 + gid;
#pragma unroll
        for (int half = 0; half < 2; half++) {
            int row = ra2 + half * 8;
            float g0 = g_gates[row * GG];
#pragma unroll
            for (int ni = 0; ni < 8; ni++) {
                int col = colBase + wn * 64 + ni * 8 + tig * 2;
                float vx, vy;
                if (zsplit == 0) {
                    vx = g0 * acc[mi][ni][half * 2 + 0];
                    vy = g0 * acc[mi][ni][half * 2 + 1];
                } else {
                    vx = acc[mi][ni][half * 2 + 0] + g0 * bias[col];
                    vy = acc[mi][ni][half * 2 + 1] + g0 * bias[col + 1];
                }
                atomicAdd(&out[(size_t)row * OO + col], vx);
                atomicAdd(&out[(size_t)row * OO + col + 1], vy);
            }
        }
    }
}

// ---------------- launcher ----------------
extern "C" void kernel_launch(void* const* d_in, const int* in_sizes, int n_in,
                              void* d_out, int out_size)
{
    const float* x      = (const float*)d_in[0];
    const float* W      = (const float*)d_in[1];
    const float* bias   = (const float*)d_in[2];
    const float* loraA  = (const float*)d_in[3];
    const float* loraB  = (const float*)d_in[4];
    const float* gw     = (const float*)d_in[5];
    // d_in[6] = bvv (unused by the reference computation)
    float* out = (float*)d_out;

    cudaFuncSetAttribute(mma_fused_kernel,
                         cudaFuncAttributeMaxDynamicSharedMemorySize, SMEM_BYTES);

    zero_out_kernel<<<NN * OO / 4 / 256, 256>>>((float4*)out);
    uint32_t* w32;  cudaGetSymbolAddress((void**)&w32, g_W32);
    uint32_t* b32;  cudaGetSymbolAddress((void**)&b32, g_B32);
    conv_tf32_kernel<<<2048, 256>>>((const float4*)W, (uint4*)w32, DD * OO / 4);
    conv_tf32_kernel<<<128, 256>>>((const float4*)loraB, (uint4*)b32, ER * OO / 4);
    transpose_A_kernel<<<512, 256>>>(loraA);
    gate_kernel<<<NN / 8, 256>>>(x, gw);
    loraA_tc_kernel<<<dim3(NSPLIT, NN / 128), 128>>>(x);
    reduce_t_kernel<<<NN * ER / 4 / 256, 256>>>();
    mma_fused_kernel<<<dim3(OO / 128, NN / 128, 2), 128, SMEM_BYTES>>>(x, bias, out);
}